// round 16
// baseline (speedup 1.0000x reference)
#include <cuda_runtime.h>
#include <cuda_bf16.h>
#include <cstdint>

#define N_NODES   100000
#define N_EDGES   1600000
#define HID       64
#define N_GRAPHS  1024
#define SCAN_BS   1024
#define SCAN_NBLK ((N_NODES + SCAN_BS - 1) / SCAN_BS)   // 98
#define POOL_CHUNK 16
#define N_CHUNKS  ((N_NODES + POOL_CHUNK - 1) / POOL_CHUNK) // 6250

// ---------------- device scratch (no allocations allowed) ----------------
__device__ int   g_rowcnt[N_NODES];        // degree histogram, later fill cursor
__device__ int   g_rowptr[N_NODES + 1];    // CSR row pointers (by dst)
__device__ int   g_csr_src[N_EDGES];       // CSR src indices
__device__ int   g_blocksums[SCAN_NBLK + 8];
__device__ float g_dinv[N_NODES];          // rsqrt(deg+1)
__device__ float g_y[(size_t)N_NODES * HID];   // GEMM output, scaled by dinv[row]
__device__ float g_h[(size_t)N_NODES * HID];   // layer activations
__device__ float g_pool[N_GRAPHS * HID];
__device__ float g_gcnt[N_GRAPHS];

// ---------------- init / degree ----------------
__global__ void k_zero() {
    int i = blockIdx.x * blockDim.x + threadIdx.x;
    if (i < N_NODES) g_rowcnt[i] = 0;
    if (i < N_GRAPHS * HID) g_pool[i] = 0.f;
    if (i < N_GRAPHS) g_gcnt[i] = 0.f;
}

__global__ void k_hist(const int* __restrict__ ei) {
    int e = blockIdx.x * blockDim.x + threadIdx.x;
    if (e < N_EDGES) {
        int dst = ei[N_EDGES + e];
        atomicAdd(&g_rowcnt[dst], 1);
    }
}

__global__ void k_dinv() {
    int i = blockIdx.x * blockDim.x + threadIdx.x;
    if (i < N_NODES) g_dinv[i] = rsqrtf((float)g_rowcnt[i] + 1.0f);
}

// ---------------- exclusive scan of rowcnt -> rowptr ----------------
__global__ void k_scan1() {
    __shared__ int wsum[32];
    int i = blockIdx.x * SCAN_BS + threadIdx.x;
    int v = (i < N_NODES) ? g_rowcnt[i] : 0;
    int lane = threadIdx.x & 31, w = threadIdx.x >> 5;
    int x = v;
    #pragma unroll
    for (int o = 1; o < 32; o <<= 1) {
        int t = __shfl_up_sync(0xffffffffu, x, o);
        if (lane >= o) x += t;
    }
    if (lane == 31) wsum[w] = x;
    __syncthreads();
    if (w == 0) {
        int s = wsum[lane];
        #pragma unroll
        for (int o = 1; o < 32; o <<= 1) {
            int t = __shfl_up_sync(0xffffffffu, s, o);
            if (lane >= o) s += t;
        }
        wsum[lane] = s;
    }
    __syncthreads();
    int excl = x - v + (w > 0 ? wsum[w - 1] : 0);
    if (i < N_NODES) g_rowptr[i] = excl;
    if (threadIdx.x == SCAN_BS - 1) g_blocksums[blockIdx.x] = excl + v;
}

__global__ void k_scan2() {
    if (threadIdx.x == 0 && blockIdx.x == 0) {
        int s = 0;
        for (int b = 0; b < SCAN_NBLK; ++b) {
            int t = g_blocksums[b];
            g_blocksums[b] = s;
            s += t;
        }
    }
}

__global__ void k_scan3() {
    int i = blockIdx.x * SCAN_BS + threadIdx.x;
    if (i < N_NODES) {
        int v = g_rowptr[i] + g_blocksums[i >> 10];
        g_rowptr[i] = v;
        g_rowcnt[i] = v;   // fill cursor
    }
    if (i == 0) g_rowptr[N_NODES] = N_EDGES;
}

__global__ void k_fill(const int* __restrict__ ei) {
    int e = blockIdx.x * blockDim.x + threadIdx.x;
    if (e < N_EDGES) {
        int src = ei[e];
        int dst = ei[N_EDGES + e];
        int pos = atomicAdd(&g_rowcnt[dst], 1);
        g_csr_src[pos] = src;
    }
}

// ---------------- graph-size histogram (chunked; batch is sorted) ----------------
__global__ void k_gcount(const int* __restrict__ batch) {
    int c = blockIdx.x * blockDim.x + threadIdx.x;
    if (c >= N_CHUNKS) return;
    int n0 = c * POOL_CHUNK;
    int n1 = min(n0 + POOL_CHUNK, N_NODES);
    int curg = batch[n0];
    float acc = 0.f;
    for (int n = n0; n < n1; ++n) {
        int g = batch[n];
        if (g != curg) { atomicAdd(&g_gcnt[curg], acc); acc = 0.f; curg = g; }
        acc += 1.0f;
    }
    atomicAdd(&g_gcnt[curg], acc);
}

// ---------------- GEMM: y[i][c] = dinv[i] * sum_k A[i][k] * W[k][c] ----------------
// 32 rows x 64 cols per CTA, 256 threads, 8 outputs/thread (4 rows x 2 cols).
template <int K>
__global__ void __launch_bounds__(256) k_gemm(const float* __restrict__ A_in,
                                              const float* __restrict__ W) {
    __shared__ float Ws[K][64];     // K=128 -> 32KB
    __shared__ float As[32][K];     // K=128 -> 16KB  (total 48KB exactly)
    const float* A = A_in ? A_in : (const float*)g_h;
    const int tid = threadIdx.x;
    const int row0 = blockIdx.x * 32;

    // load W (K x 64)
    for (int i = tid; i < K * 16; i += 256)
        ((float4*)&Ws[0][0])[i] = ((const float4*)W)[i];

    // load A tile (32 x K), zero-padded past N_NODES
    const float4* A4 = (const float4*)A;
    for (int i = tid; i < 32 * (K / 4); i += 256) {
        int r  = i / (K / 4);
        int c4 = i % (K / 4);
        int grow = row0 + r;
        float4 v = (grow < N_NODES) ? A4[(size_t)grow * (K / 4) + c4]
                                    : make_float4(0.f, 0.f, 0.f, 0.f);
        ((float4*)&As[r][0])[c4] = v;
    }
    __syncthreads();

    const int cb = (tid & 31) * 2;   // column pair base (0..62)
    const int r0 = tid >> 5;         // 0..7
    float acc[4][2];
    #pragma unroll
    for (int r = 0; r < 4; ++r) { acc[r][0] = 0.f; acc[r][1] = 0.f; }

    #pragma unroll 4
    for (int k = 0; k < K; ++k) {
        float2 w = *(const float2*)&Ws[k][cb];
        #pragma unroll
        for (int r = 0; r < 4; ++r) {
            float a = As[r0 + r * 8][k];   // broadcast within warp
            acc[r][0] = fmaf(a, w.x, acc[r][0]);
            acc[r][1] = fmaf(a, w.y, acc[r][1]);
        }
    }

    #pragma unroll
    for (int r = 0; r < 4; ++r) {
        int grow = row0 + r0 + r * 8;
        if (grow < N_NODES) {
            float d = g_dinv[grow];
            *(float2*)&g_y[(size_t)grow * HID + cb] =
                make_float2(acc[r][0] * d, acc[r][1] * d);
        }
    }
}

// ---------------- gather + self-loop + bias (+relu): warp per node ----------------
__global__ void __launch_bounds__(256) k_gather(const float* __restrict__ bias, int relu) {
    int node = (blockIdx.x * blockDim.x + threadIdx.x) >> 5;
    int lane = threadIdx.x & 31;
    if (node >= N_NODES) return;
    int beg = g_rowptr[node];
    int end = g_rowptr[node + 1];
    const float2* Y = (const float2*)g_y;

    float2 acc = make_float2(0.f, 0.f);
    int e = beg;
    for (; e + 4 <= end; e += 4) {
        int s0 = g_csr_src[e + 0];
        int s1 = g_csr_src[e + 1];
        int s2 = g_csr_src[e + 2];
        int s3 = g_csr_src[e + 3];
        float2 v0 = Y[s0 * 32 + lane];
        float2 v1 = Y[s1 * 32 + lane];
        float2 v2 = Y[s2 * 32 + lane];
        float2 v3 = Y[s3 * 32 + lane];
        acc.x += (v0.x + v1.x) + (v2.x + v3.x);
        acc.y += (v0.y + v1.y) + (v2.y + v3.y);
    }
    for (; e < end; ++e) {
        int s = g_csr_src[e];
        float2 v = Y[s * 32 + lane];
        acc.x += v.x; acc.y += v.y;
    }
    // self-loop contribution: + y[node]
    float2 self = Y[node * 32 + lane];
    acc.x += self.x; acc.y += self.y;

    float d = g_dinv[node];
    float2 b = ((const float2*)bias)[lane];
    float ox = fmaf(d, acc.x, b.x);
    float oy = fmaf(d, acc.y, b.y);
    if (relu) { ox = fmaxf(ox, 0.f); oy = fmaxf(oy, 0.f); }
    ((float2*)g_h)[node * 32 + lane] = make_float2(ox, oy);
}

// ---------------- pooling: chunked segment sum (batch sorted) ----------------
__global__ void k_pool(const int* __restrict__ batch) {
    int t = blockIdx.x * blockDim.x + threadIdx.x;
    if (t >= N_CHUNKS * HID) return;
    int f = t & 63;
    int chunk = t >> 6;
    int n0 = chunk * POOL_CHUNK;
    int n1 = min(n0 + POOL_CHUNK, N_NODES);
    int curg = batch[n0];
    float acc = 0.f;
    for (int n = n0; n < n1; ++n) {
        int g = batch[n];
        if (g != curg) { atomicAdd(&g_pool[curg * HID + f], acc); acc = 0.f; curg = g; }
        acc += g_h[(size_t)n * HID + f];
    }
    atomicAdd(&g_pool[curg * HID + f], acc);
}

// ---------------- final: out[g] = (pool[g]/max(cnt,1)) . Wl + bl ----------------
__global__ void k_final(const float* __restrict__ Wl, const float* __restrict__ bl,
                        float* __restrict__ out) {
    int g = (blockIdx.x * blockDim.x + threadIdx.x) >> 5;
    int lane = threadIdx.x & 31;
    if (g >= N_GRAPHS) return;
    float c = fmaxf(g_gcnt[g], 1.0f);
    float2 p = ((const float2*)g_pool)[g * 32 + lane];
    float2 w = ((const float2*)Wl)[lane];
    float s = (p.x * w.x + p.y * w.y) / c;
    #pragma unroll
    for (int o = 16; o > 0; o >>= 1) s += __shfl_down_sync(0xffffffffu, s, o);
    if (lane == 0) out[g] = s + bl[0];
}

// ---------------- launch ----------------
extern "C" void kernel_launch(void* const* d_in, const int* in_sizes, int n_in,
                              void* d_out, int out_size) {
    const float* x     = (const float*)d_in[0];
    const int*   ei    = (const int*)d_in[1];     // int32: JAX canonicalizes int64->int32
    const int*   batch = (const int*)d_in[2];     // int32
    const float* W1    = (const float*)d_in[3];
    const float* b1    = (const float*)d_in[4];
    const float* W2    = (const float*)d_in[5];
    const float* b2    = (const float*)d_in[6];
    const float* W3    = (const float*)d_in[7];
    const float* b3    = (const float*)d_in[8];
    const float* Wl    = (const float*)d_in[9];
    const float* bl    = (const float*)d_in[10];
    float* out = (float*)d_out;

    const int TB = 256;
    const int nb_nodes = (N_NODES + TB - 1) / TB;           // 391
    const int nb_edges = (N_EDGES + TB - 1) / TB;           // 6250
    const int nb_gemm  = (N_NODES + 31) / 32;               // 3125
    const int nb_gath  = (N_NODES * 32 + TB - 1) / TB;      // 12500
    const int nb_pool  = (N_CHUNKS * HID + TB - 1) / TB;    // 1563
    const int nb_gcnt  = (N_CHUNKS + TB - 1) / TB;          // 25
    const int nb_fin   = (N_GRAPHS * 32 + TB - 1) / TB;     // 128

    // ---- graph structure (once per call) ----
    k_zero<<<nb_nodes, TB>>>();
    k_hist<<<nb_edges, TB>>>(ei);
    k_gcount<<<nb_gcnt, TB>>>(batch);
    k_dinv<<<nb_nodes, TB>>>();
    k_scan1<<<SCAN_NBLK, SCAN_BS>>>();
    k_scan2<<<1, 32>>>();
    k_scan3<<<SCAN_NBLK, SCAN_BS>>>();
    k_fill<<<nb_edges, TB>>>(ei);

    // ---- layer 1: x[100000,128] @ W1 -> relu ----
    k_gemm<128><<<nb_gemm, TB>>>(x, W1);
    k_gather<<<nb_gath, TB>>>(b1, 1);

    // ---- layer 2 ----
    k_gemm<64><<<nb_gemm, TB>>>(nullptr, W2);   // A = g_h
    k_gather<<<nb_gath, TB>>>(b2, 1);

    // ---- layer 3 (no relu) ----
    k_gemm<64><<<nb_gemm, TB>>>(nullptr, W3);
    k_gather<<<nb_gath, TB>>>(b3, 0);

    // ---- mean pool + linear head ----
    k_pool<<<nb_pool, TB>>>(batch);
    k_final<<<nb_fin, TB>>>(Wl, bl, out);
}

// round 17
// speedup vs baseline: 1.0099x; 1.0099x over previous
#include <cuda_runtime.h>
#include <cuda_bf16.h>
#include <cstdint>

#define N_NODES   100000
#define N_EDGES   1600000
#define HID       64
#define N_GRAPHS  1024
#define SCAN_BS   1024
#define SCAN_NBLK ((N_NODES + SCAN_BS - 1) / SCAN_BS)   // 98
#define POOL_CHUNK 16
#define N_CHUNKS  ((N_NODES + POOL_CHUNK - 1) / POOL_CHUNK) // 6250

// ---------------- device scratch (no allocations allowed) ----------------
__device__ int   g_rowcnt[N_NODES];        // degree histogram, later fill cursor
__device__ int   g_rowptr[N_NODES + 1];    // CSR row pointers (by dst)
__device__ int   g_csr_src[N_EDGES];       // CSR src indices
__device__ int   g_blocksums[SCAN_NBLK + 8];
__device__ float g_dinv[N_NODES];          // rsqrt(deg+1)
__device__ float g_y[(size_t)N_NODES * HID];   // GEMM output, scaled by dinv[row]
__device__ float g_h[(size_t)N_NODES * HID];   // layer activations
__device__ float g_pool[N_GRAPHS * HID];
__device__ float g_gcnt[N_GRAPHS];

// ---------------- init / degree ----------------
__global__ void k_zero() {
    int i = blockIdx.x * blockDim.x + threadIdx.x;
    if (i < N_NODES) g_rowcnt[i] = 0;
    if (i < N_GRAPHS * HID) g_pool[i] = 0.f;
    if (i < N_GRAPHS) g_gcnt[i] = 0.f;
}

__global__ void k_hist(const int* __restrict__ ei) {
    int e = blockIdx.x * blockDim.x + threadIdx.x;
    if (e < N_EDGES) {
        int dst = ei[N_EDGES + e];
        atomicAdd(&g_rowcnt[dst], 1);
    }
}

__global__ void k_dinv() {
    int i = blockIdx.x * blockDim.x + threadIdx.x;
    if (i < N_NODES) g_dinv[i] = rsqrtf((float)g_rowcnt[i] + 1.0f);
}

// ---------------- exclusive scan of rowcnt -> rowptr ----------------
__global__ void k_scan1() {
    __shared__ int wsum[32];
    int i = blockIdx.x * SCAN_BS + threadIdx.x;
    int v = (i < N_NODES) ? g_rowcnt[i] : 0;
    int lane = threadIdx.x & 31, w = threadIdx.x >> 5;
    int x = v;
    #pragma unroll
    for (int o = 1; o < 32; o <<= 1) {
        int t = __shfl_up_sync(0xffffffffu, x, o);
        if (lane >= o) x += t;
    }
    if (lane == 31) wsum[w] = x;
    __syncthreads();
    if (w == 0) {
        int s = wsum[lane];
        #pragma unroll
        for (int o = 1; o < 32; o <<= 1) {
            int t = __shfl_up_sync(0xffffffffu, s, o);
            if (lane >= o) s += t;
        }
        wsum[lane] = s;
    }
    __syncthreads();
    int excl = x - v + (w > 0 ? wsum[w - 1] : 0);
    if (i < N_NODES) g_rowptr[i] = excl;
    if (threadIdx.x == SCAN_BS - 1) g_blocksums[blockIdx.x] = excl + v;
}

__global__ void k_scan2() {
    if (threadIdx.x == 0 && blockIdx.x == 0) {
        int s = 0;
        for (int b = 0; b < SCAN_NBLK; ++b) {
            int t = g_blocksums[b];
            g_blocksums[b] = s;
            s += t;
        }
    }
}

__global__ void k_scan3() {
    int i = blockIdx.x * SCAN_BS + threadIdx.x;
    if (i < N_NODES) {
        int v = g_rowptr[i] + g_blocksums[i >> 10];
        g_rowptr[i] = v;
        g_rowcnt[i] = v;   // fill cursor
    }
    if (i == 0) g_rowptr[N_NODES] = N_EDGES;
}

__global__ void k_fill(const int* __restrict__ ei) {
    int e = blockIdx.x * blockDim.x + threadIdx.x;
    if (e < N_EDGES) {
        int src = ei[e];
        int dst = ei[N_EDGES + e];
        int pos = atomicAdd(&g_rowcnt[dst], 1);
        g_csr_src[pos] = src;
    }
}

// ---------------- graph-size histogram (chunked; batch is sorted) ----------------
__global__ void k_gcount(const int* __restrict__ batch) {
    int c = blockIdx.x * blockDim.x + threadIdx.x;
    if (c >= N_CHUNKS) return;
    int n0 = c * POOL_CHUNK;
    int n1 = min(n0 + POOL_CHUNK, N_NODES);
    int curg = batch[n0];
    float acc = 0.f;
    for (int n = n0; n < n1; ++n) {
        int g = batch[n];
        if (g != curg) { atomicAdd(&g_gcnt[curg], acc); acc = 0.f; curg = g; }
        acc += 1.0f;
    }
    atomicAdd(&g_gcnt[curg], acc);
}

// ---------------- GEMM: y[i][c] = dinv[i] * sum_k A[i][k] * W[k][c] ----------------
// 32 rows x 64 cols per CTA, 256 threads, 8 outputs/thread (4 rows x 2 cols).
template <int K>
__global__ void __launch_bounds__(256) k_gemm(const float* __restrict__ A_in,
                                              const float* __restrict__ W) {
    __shared__ float Ws[K][64];     // K=128 -> 32KB
    __shared__ float As[32][K];     // K=128 -> 16KB  (total 48KB exactly)
    const float* A = A_in ? A_in : (const float*)g_h;
    const int tid = threadIdx.x;
    const int row0 = blockIdx.x * 32;

    // load W (K x 64)
    for (int i = tid; i < K * 16; i += 256)
        ((float4*)&Ws[0][0])[i] = ((const float4*)W)[i];

    // load A tile (32 x K), zero-padded past N_NODES
    const float4* A4 = (const float4*)A;
    for (int i = tid; i < 32 * (K / 4); i += 256) {
        int r  = i / (K / 4);
        int c4 = i % (K / 4);
        int grow = row0 + r;
        float4 v = (grow < N_NODES) ? A4[(size_t)grow * (K / 4) + c4]
                                    : make_float4(0.f, 0.f, 0.f, 0.f);
        ((float4*)&As[r][0])[c4] = v;
    }
    __syncthreads();

    const int cb = (tid & 31) * 2;   // column pair base (0..62)
    const int r0 = tid >> 5;         // 0..7
    float acc[4][2];
    #pragma unroll
    for (int r = 0; r < 4; ++r) { acc[r][0] = 0.f; acc[r][1] = 0.f; }

    #pragma unroll 4
    for (int k = 0; k < K; ++k) {
        float2 w = *(const float2*)&Ws[k][cb];
        #pragma unroll
        for (int r = 0; r < 4; ++r) {
            float a = As[r0 + r * 8][k];   // broadcast within warp
            acc[r][0] = fmaf(a, w.x, acc[r][0]);
            acc[r][1] = fmaf(a, w.y, acc[r][1]);
        }
    }

    #pragma unroll
    for (int r = 0; r < 4; ++r) {
        int grow = row0 + r0 + r * 8;
        if (grow < N_NODES) {
            float d = g_dinv[grow];
            *(float2*)&g_y[(size_t)grow * HID + cb] =
                make_float2(acc[r][0] * d, acc[r][1] * d);
        }
    }
}

// ---------------- gather + self-loop + bias (+relu): warp per node ----------------
__global__ void __launch_bounds__(256) k_gather(const float* __restrict__ bias, int relu) {
    int node = (blockIdx.x * blockDim.x + threadIdx.x) >> 5;
    int lane = threadIdx.x & 31;
    if (node >= N_NODES) return;
    int beg = g_rowptr[node];
    int end = g_rowptr[node + 1];
    const float2* Y = (const float2*)g_y;

    float2 acc = make_float2(0.f, 0.f);
    int e = beg;
    for (; e + 4 <= end; e += 4) {
        int s0 = g_csr_src[e + 0];
        int s1 = g_csr_src[e + 1];
        int s2 = g_csr_src[e + 2];
        int s3 = g_csr_src[e + 3];
        float2 v0 = Y[s0 * 32 + lane];
        float2 v1 = Y[s1 * 32 + lane];
        float2 v2 = Y[s2 * 32 + lane];
        float2 v3 = Y[s3 * 32 + lane];
        acc.x += (v0.x + v1.x) + (v2.x + v3.x);
        acc.y += (v0.y + v1.y) + (v2.y + v3.y);
    }
    for (; e < end; ++e) {
        int s = g_csr_src[e];
        float2 v = Y[s * 32 + lane];
        acc.x += v.x; acc.y += v.y;
    }
    // self-loop contribution: + y[node]
    float2 self = Y[node * 32 + lane];
    acc.x += self.x; acc.y += self.y;

    float d = g_dinv[node];
    float2 b = ((const float2*)bias)[lane];
    float ox = fmaf(d, acc.x, b.x);
    float oy = fmaf(d, acc.y, b.y);
    if (relu) { ox = fmaxf(ox, 0.f); oy = fmaxf(oy, 0.f); }
    ((float2*)g_h)[node * 32 + lane] = make_float2(ox, oy);
}

// ---------------- pooling: chunked segment sum (batch sorted) ----------------
__global__ void k_pool(const int* __restrict__ batch) {
    int t = blockIdx.x * blockDim.x + threadIdx.x;
    if (t >= N_CHUNKS * HID) return;
    int f = t & 63;
    int chunk = t >> 6;
    int n0 = chunk * POOL_CHUNK;
    int n1 = min(n0 + POOL_CHUNK, N_NODES);
    int curg = batch[n0];
    float acc = 0.f;
    for (int n = n0; n < n1; ++n) {
        int g = batch[n];
        if (g != curg) { atomicAdd(&g_pool[curg * HID + f], acc); acc = 0.f; curg = g; }
        acc += g_h[(size_t)n * HID + f];
    }
    atomicAdd(&g_pool[curg * HID + f], acc);
}

// ---------------- final: out[g] = (pool[g]/max(cnt,1)) . Wl + bl ----------------
__global__ void k_final(const float* __restrict__ Wl, const float* __restrict__ bl,
                        float* __restrict__ out) {
    int g = (blockIdx.x * blockDim.x + threadIdx.x) >> 5;
    int lane = threadIdx.x & 31;
    if (g >= N_GRAPHS) return;
    float c = fmaxf(g_gcnt[g], 1.0f);
    float2 p = ((const float2*)g_pool)[g * 32 + lane];
    float2 w = ((const float2*)Wl)[lane];
    float s = (p.x * w.x + p.y * w.y) / c;
    #pragma unroll
    for (int o = 16; o > 0; o >>= 1) s += __shfl_down_sync(0xffffffffu, s, o);
    if (lane == 0) out[g] = s + bl[0];
}

// ---------------- launch ----------------
extern "C" void kernel_launch(void* const* d_in, const int* in_sizes, int n_in,
                              void* d_out, int out_size) {
    const float* x     = (const float*)d_in[0];
    const int*   ei    = (const int*)d_in[1];     // int32: JAX canonicalizes int64->int32
    const int*   batch = (const int*)d_in[2];     // int32
    const float* W1    = (const float*)d_in[3];
    const float* b1    = (const float*)d_in[4];
    const float* W2    = (const float*)d_in[5];
    const float* b2    = (const float*)d_in[6];
    const float* W3    = (const float*)d_in[7];
    const float* b3    = (const float*)d_in[8];
    const float* Wl    = (const float*)d_in[9];
    const float* bl    = (const float*)d_in[10];
    float* out = (float*)d_out;

    const int TB = 256;
    const int nb_nodes = (N_NODES + TB - 1) / TB;           // 391
    const int nb_edges = (N_EDGES + TB - 1) / TB;           // 6250
    const int nb_gemm  = (N_NODES + 31) / 32;               // 3125
    const int nb_gath  = (N_NODES * 32 + TB - 1) / TB;      // 12500
    const int nb_pool  = (N_CHUNKS * HID + TB - 1) / TB;    // 1563
    const int nb_gcnt  = (N_CHUNKS + TB - 1) / TB;          // 25
    const int nb_fin   = (N_GRAPHS * 32 + TB - 1) / TB;     // 128

    // ---- graph structure (once per call) ----
    k_zero<<<nb_nodes, TB>>>();
    k_hist<<<nb_edges, TB>>>(ei);
    k_gcount<<<nb_gcnt, TB>>>(batch);
    k_dinv<<<nb_nodes, TB>>>();
    k_scan1<<<SCAN_NBLK, SCAN_BS>>>();
    k_scan2<<<1, 32>>>();
    k_scan3<<<SCAN_NBLK, SCAN_BS>>>();
    k_fill<<<nb_edges, TB>>>(ei);

    // ---- layer 1: x[100000,128] @ W1 -> relu ----
    k_gemm<128><<<nb_gemm, TB>>>(x, W1);
    k_gather<<<nb_gath, TB>>>(b1, 1);

    // ---- layer 2 ----
    k_gemm<64><<<nb_gemm, TB>>>(nullptr, W2);   // A = g_h
    k_gather<<<nb_gath, TB>>>(b2, 1);

    // ---- layer 3 (no relu) ----
    k_gemm<64><<<nb_gemm, TB>>>(nullptr, W3);
    k_gather<<<nb_gath, TB>>>(b3, 0);

    // ---- mean pool + linear head ----
    k_pool<<<nb_pool, TB>>>(batch);
    k_final<<<nb_fin, TB>>>(Wl, bl, out);
}